// round 8
// baseline (speedup 1.0000x reference)
#include <cuda_runtime.h>
#include <cstdint>
#include <cstddef>

// Problem constants
#define Bsz 64
#define Hd  512
#define TVv 512
#define TTt 64

// Tile config for the fused GEMM kernel
#define TM  64
#define TN  128
#define TKC 16
#define NT  (Hd / TN)   // 4 N-tiles

typedef unsigned long long ull;

// ---------------- device scratch (no allocation allowed) ----------------
__device__ float g_Uhv [Bsz*Hd];
__device__ float g_Uht [Bsz*Hd];
__device__ float g_Wbs [Bsz*Hd];
__device__ float g_hWhh[Bsz*Hd];
__device__ float g_WveT[Hd*Hd];
__device__ float g_WqeT[Hd*Hd];
__device__ float g_part_v[NT*Bsz*TVv];
__device__ float g_part_t[NT*Bsz*TTt];
__device__ float g_av [Bsz*TVv];
__device__ float g_at [Bsz*TTt];
__device__ float g_hv [Bsz*Hd];
__device__ float g_ht [Bsz*Hd];
__device__ float g_hv2[Bsz*Hd];
__device__ float g_ht2[Bsz*Hd];
__device__ float g_mv1[Bsz*Hd];
__device__ float g_mt1[Bsz*Hd];
__device__ float g_logits[2*Bsz];
__device__ float g_beta[2];

// ---------------- packed fp32x2 helpers (FFMA2 path, sm_100+) ----------------
__device__ __forceinline__ ull dup2(float x) {
    ull r; unsigned u = __float_as_uint(x);
#if defined(__CUDA_ARCH__) && (__CUDA_ARCH__ >= 1000)
    asm("mov.b64 %0, {%1, %1};" : "=l"(r) : "r"(u));
#else
    r = ((ull)u << 32) | (ull)u;
#endif
    return r;
}

__device__ __forceinline__ void fma2(ull &d, ull a, ull b) {
#if defined(__CUDA_ARCH__) && (__CUDA_ARCH__ >= 1000)
    asm("fma.rn.f32x2 %0, %1, %2, %3;" : "=l"(d) : "l"(a), "l"(b), "l"(d));
#else
    float ax = __uint_as_float((unsigned)(a & 0xffffffffu));
    float ay = __uint_as_float((unsigned)(a >> 32));
    float bx = __uint_as_float((unsigned)(b & 0xffffffffu));
    float by = __uint_as_float((unsigned)(b >> 32));
    float dx = __uint_as_float((unsigned)(d & 0xffffffffu));
    float dy = __uint_as_float((unsigned)(d >> 32));
    dx = fmaf(ax, bx, dx); dy = fmaf(ay, by, dy);
    d = ((ull)__float_as_uint(dy) << 32) | (ull)__float_as_uint(dx);
#endif
}

__device__ __forceinline__ float2 u2f(ull v) {
    float2 f;
    f.x = __uint_as_float((unsigned)(v & 0xffffffffu));
    f.y = __uint_as_float((unsigned)(v >> 32));
    return f;
}

// ---------------- main tile kernel ----------------
// Computes a [TM x TN] tile of A[rows,512] @ W[512,512].
// epi == 0: C[m,j] = acc + bias[j](opt) + addmat[m,j](opt)
// epi == 1: fused score epilogue:
//   partial[ntile*rows + m] = sum_{j in tile} V[j] * tanh(acc + Uh[b,j] + sbias[j])
//   (b = m0 / T, valid because TM=64 divides both Tv=512 and Tt=64)
__global__ void __launch_bounds__(256, 2)
tile_gemm(const float* __restrict__ A, const float* __restrict__ W, int epi,
          float* __restrict__ C, const float* __restrict__ bias, const float* __restrict__ addmat,
          const float* __restrict__ Uh, const float* __restrict__ sbias,
          const float* __restrict__ V, float* __restrict__ partial, int T, int rows)
{
    __shared__ __align__(16) float As[TKC][TM + 4];   // +4 pad keeps 16B alignment (stride 272B)
    __shared__ __align__(16) float Bs[TKC][TN];

    const int tid = threadIdx.x;
    const int tx = tid & 15;      // 16 col-groups of 8 cols
    const int ty = tid >> 4;      // 16 row-groups of 4 rows
    const int n0 = blockIdx.x * TN;
    const int m0 = blockIdx.y * TM;

    const float* Ab = A + (size_t)m0 * Hd;

    float rA[4], rB[8];
    // prefetch k-chunk 0
#pragma unroll
    for (int i = 0; i < 4; i++) { int e = tid + i*256; rA[i] = Ab[(size_t)(e >> 4)*Hd + (e & 15)]; }
#pragma unroll
    for (int i = 0; i < 8; i++) { int e = tid + i*256; rB[i] = W[(size_t)(e >> 7)*Hd + n0 + (e & 127)]; }

    ull c2[4][4];
#pragma unroll
    for (int r = 0; r < 4; r++)
#pragma unroll
        for (int p = 0; p < 4; p++) c2[r][p] = 0ull;

    for (int kt = 0; kt < Hd; kt += TKC) {
        __syncthreads();
#pragma unroll
        for (int i = 0; i < 4; i++) { int e = tid + i*256; As[e & 15][e >> 4]  = rA[i]; }
#pragma unroll
        for (int i = 0; i < 8; i++) { int e = tid + i*256; Bs[e >> 7][e & 127] = rB[i]; }
        __syncthreads();

        const int ktn = kt + TKC;
        if (ktn < Hd) {
#pragma unroll
            for (int i = 0; i < 4; i++) { int e = tid + i*256; rA[i] = Ab[(size_t)(e >> 4)*Hd + ktn + (e & 15)]; }
#pragma unroll
            for (int i = 0; i < 8; i++) { int e = tid + i*256; rB[i] = W[(size_t)(ktn + (e >> 7))*Hd + n0 + (e & 127)]; }
        }

#pragma unroll
        for (int k = 0; k < TKC; k++) {
            float4 av4 = *(const float4*)&As[k][ty*4];
            const ull* bp = (const ull*)&Bs[k][tx*8];
            ull pb0 = bp[0], pb1 = bp[1], pb2 = bp[2], pb3 = bp[3];
            ull a0 = dup2(av4.x), a1 = dup2(av4.y), a2 = dup2(av4.z), a3 = dup2(av4.w);
            fma2(c2[0][0], a0, pb0); fma2(c2[0][1], a0, pb1); fma2(c2[0][2], a0, pb2); fma2(c2[0][3], a0, pb3);
            fma2(c2[1][0], a1, pb0); fma2(c2[1][1], a1, pb1); fma2(c2[1][2], a1, pb2); fma2(c2[1][3], a1, pb3);
            fma2(c2[2][0], a2, pb0); fma2(c2[2][1], a2, pb1); fma2(c2[2][2], a2, pb2); fma2(c2[2][3], a2, pb3);
            fma2(c2[3][0], a3, pb0); fma2(c2[3][1], a3, pb1); fma2(c2[3][2], a3, pb2); fma2(c2[3][3], a3, pb3);
        }
    }

    if (epi == 0) {
#pragma unroll
        for (int r = 0; r < 4; r++) {
            int m = m0 + ty*4 + r;
#pragma unroll
            for (int p = 0; p < 4; p++) {
                float2 v2 = u2f(c2[r][p]);
                int j0 = n0 + tx*8 + p*2;
                float x0 = v2.x, x1 = v2.y;
                if (bias)   { x0 += bias[j0];                      x1 += bias[j0+1]; }
                if (addmat) { x0 += addmat[(size_t)m*Hd + j0];     x1 += addmat[(size_t)m*Hd + j0 + 1]; }
                C[(size_t)m*Hd + j0]     = x0;
                C[(size_t)m*Hd + j0 + 1] = x1;
            }
        }
    } else {
        const int b = m0 / T;
        const float* UhR = Uh + (size_t)b * Hd;
        float s[4] = {0.f, 0.f, 0.f, 0.f};
#pragma unroll
        for (int r = 0; r < 4; r++) {
#pragma unroll
            for (int p = 0; p < 4; p++) {
                float2 v2 = u2f(c2[r][p]);
                int j0 = n0 + tx*8 + p*2;
                s[r] += V[j0]     * tanhf(v2.x + UhR[j0]     + sbias[j0]);
                s[r] += V[j0 + 1] * tanhf(v2.y + UhR[j0 + 1] + sbias[j0 + 1]);
            }
        }
        // reduce across the 16 tx lanes (each warp holds two independent 16-lane groups)
#pragma unroll
        for (int off = 8; off; off >>= 1) {
#pragma unroll
            for (int r = 0; r < 4; r++)
                s[r] += __shfl_xor_sync(0xffffffffu, s[r], off, 16);
        }
        if (tx == 0) {
            int nt = blockIdx.x;
#pragma unroll
            for (int r = 0; r < 4; r++)
                partial[(size_t)nt * rows + m0 + ty*4 + r] = s[r];
        }
    }
}

// ---------------- transpose 512x512 ----------------
__global__ void transpose_k(const float* __restrict__ in, float* __restrict__ out) {
    __shared__ float tile[32][33];
    int x  = blockIdx.x*32 + threadIdx.x;
    int y0 = blockIdx.y*32;
#pragma unroll
    for (int i = threadIdx.y; i < 32; i += 8)
        tile[i][threadIdx.x] = in[(size_t)(y0 + i)*Hd + x];
    __syncthreads();
    int xo  = y0 + threadIdx.x;
    int yo0 = blockIdx.x*32;
#pragma unroll
    for (int i = threadIdx.y; i < 32; i += 8)
        out[(size_t)(yo0 + i)*Hd + xo] = tile[threadIdx.x][i];
}

// ---------------- softmax over T per batch (sums NT partials first) ----------------
__global__ void softmax_k(const float* __restrict__ part, float* __restrict__ out, int T, int rows) {
    __shared__ float buf[TVv];
    __shared__ float red[256];
    const int b = blockIdx.x, tid = threadIdx.x;
    for (int t = tid; t < T; t += 256) {
        float s = 0.f;
#pragma unroll
        for (int n = 0; n < NT; n++) s += part[(size_t)n*rows + b*T + t];
        buf[t] = s;
    }
    __syncthreads();
    float m = -1e30f;
    for (int t = tid; t < T; t += 256) m = fmaxf(m, buf[t]);
    red[tid] = m; __syncthreads();
    for (int o = 128; o > 0; o >>= 1) { if (tid < o) red[tid] = fmaxf(red[tid], red[tid + o]); __syncthreads(); }
    m = red[0]; __syncthreads();
    float s = 0.f;
    for (int t = tid; t < T; t += 256) { float e = expf(buf[t] - m); buf[t] = e; s += e; }
    red[tid] = s; __syncthreads();
    for (int o = 128; o > 0; o >>= 1) { if (tid < o) red[tid] += red[tid + o]; __syncthreads(); }
    float inv = 1.f / red[0];
    for (int t = tid; t < T; t += 256) out[b*T + t] = buf[t] * inv;
}

// ---------------- weighted sum: out[b,:] = a[b,:] @ F[b,:,:] ----------------
__global__ void wsum_k(const float* __restrict__ F, const float* __restrict__ a,
                       float* __restrict__ out, int T) {
    __shared__ float as_[TVv];
    const int b = blockIdx.x;
    const int j = blockIdx.y*128 + threadIdx.x;
    for (int t = threadIdx.x; t < T; t += 128) as_[t] = a[b*T + t];
    __syncthreads();
    const float* Fb = F + (size_t)b * T * Hd + j;
    float acc = 0.f;
#pragma unroll 8
    for (int t = 0; t < T; t++) acc += as_[t] * Fb[(size_t)t * Hd];
    out[b*Hd + j] = acc;
}

// ---------------- gating logits: logits[r] = tanh(row_r) . wb ----------------
__global__ void logits_k(const float* __restrict__ mv1, const float* __restrict__ mt1,
                         const float* __restrict__ wb, float* __restrict__ lg) {
    __shared__ float red[128];
    const int r = blockIdx.x, tid = threadIdx.x;
    const float* row = (r < Bsz) ? (mv1 + (size_t)r*Hd) : (mt1 + (size_t)(r - Bsz)*Hd);
    float s = 0.f;
    for (int k = tid; k < Hd; k += 128) s += tanhf(row[k]) * wb[k];
    red[tid] = s; __syncthreads();
    for (int o = 64; o > 0; o >>= 1) { if (tid < o) red[tid] += red[tid + o]; __syncthreads(); }
    if (tid == 0) lg[r] = red[0];
}

// ---------------- beta = softmax(logits)[0..1] ----------------
__global__ void beta_k(const float* __restrict__ lg, float* __restrict__ beta) {
    __shared__ float red[128];
    __shared__ float ev[128];
    const int tid = threadIdx.x;
    float l = lg[tid];
    red[tid] = l; __syncthreads();
    for (int o = 64; o > 0; o >>= 1) { if (tid < o) red[tid] = fmaxf(red[tid], red[tid + o]); __syncthreads(); }
    float m = red[0]; __syncthreads();
    float e = expf(l - m);
    ev[tid] = e; red[tid] = e; __syncthreads();
    for (int o = 64; o > 0; o >>= 1) { if (tid < o) red[tid] += red[tid + o]; __syncthreads(); }
    if (tid == 0) { beta[0] = ev[0] / red[0]; beta[1] = ev[1] / red[0]; }
}

// ---------------- final output ----------------
__global__ void final_k(const float* __restrict__ hWhh, const float* __restrict__ hv2,
                        const float* __restrict__ ht2, const float* __restrict__ bh,
                        const float* __restrict__ beta, float* __restrict__ out) {
    const int idx = blockIdx.x * blockDim.x + threadIdx.x;
    out[idx] = tanhf(hWhh[idx] + beta[0]*hv2[idx] + beta[1]*ht2[idx] + bh[idx & (Hd - 1)]);
}

// ---------------- host launcher ----------------
extern "C" void kernel_launch(void* const* d_in, const int* in_sizes, int n_in,
                              void* d_out, int out_size) {
    const float* h   = (const float*)d_in[0];
    const float* F   = (const float*)d_in[1];   // hidden_frames [B,Tv,H]
    const float* Tx  = (const float*)d_in[2];   // hidden_text   [B,Tt,H]
    const float* Wav = (const float*)d_in[3];
    const float* Wat = (const float*)d_in[4];
    const float* Uav = (const float*)d_in[5];
    const float* Uat = (const float*)d_in[6];
    const float* Vav = (const float*)d_in[7];
    const float* Vat = (const float*)d_in[8];
    const float* bav = (const float*)d_in[9];
    const float* bat = (const float*)d_in[10];
    const float* Whh = (const float*)d_in[11];
    const float* bh  = (const float*)d_in[12];
    const float* Wve = (const float*)d_in[13];
    const float* bve = (const float*)d_in[14];
    const float* Wqe = (const float*)d_in[15];
    const float* bqe = (const float*)d_in[16];
    const float* Wb  = (const float*)d_in[17];
    const float* Vbv = (const float*)d_in[18];
    const float* Vbt = (const float*)d_in[19];
    const float* bbv = (const float*)d_in[20];
    const float* bbt = (const float*)d_in[21];
    const float* wb  = (const float*)d_in[22];
    float* out = (float*)d_out;

    float *Uhv, *Uht, *Wbs, *hWhh, *WveT, *WqeT, *pv, *pt, *av, *at,
          *hv, *ht, *hv2, *ht2, *mv1, *mt1, *lg, *beta;
    cudaGetSymbolAddress((void**)&Uhv,  g_Uhv);
    cudaGetSymbolAddress((void**)&Uht,  g_Uht);
    cudaGetSymbolAddress((void**)&Wbs,  g_Wbs);
    cudaGetSymbolAddress((void**)&hWhh, g_hWhh);
    cudaGetSymbolAddress((void**)&WveT, g_WveT);
    cudaGetSymbolAddress((void**)&WqeT, g_WqeT);
    cudaGetSymbolAddress((void**)&pv,   g_part_v);
    cudaGetSymbolAddress((void**)&pt,   g_part_t);
    cudaGetSymbolAddress((void**)&av,   g_av);
    cudaGetSymbolAddress((void**)&at,   g_at);
    cudaGetSymbolAddress((void**)&hv,   g_hv);
    cudaGetSymbolAddress((void**)&ht,   g_ht);
    cudaGetSymbolAddress((void**)&hv2,  g_hv2);
    cudaGetSymbolAddress((void**)&ht2,  g_ht2);
    cudaGetSymbolAddress((void**)&mv1,  g_mv1);
    cudaGetSymbolAddress((void**)&mt1,  g_mt1);
    cudaGetSymbolAddress((void**)&lg,   g_logits);
    cudaGetSymbolAddress((void**)&beta, g_beta);

    const dim3 blk(256);

    // Transposes for the .T encoders
    transpose_k<<<dim3(16,16), dim3(32,8)>>>(Wve, WveT);
    transpose_k<<<dim3(16,16), dim3(32,8)>>>(Wqe, WqeT);

    // Small conditioning GEMMs: h @ {Uav, Uat, Wb, Whh}
    tile_gemm<<<dim3(NT,1), blk>>>(h, Uav, 0, Uhv,  nullptr, nullptr, nullptr, nullptr, nullptr, nullptr, 1, Bsz);
    tile_gemm<<<dim3(NT,1), blk>>>(h, Uat, 0, Uht,  nullptr, nullptr, nullptr, nullptr, nullptr, nullptr, 1, Bsz);
    tile_gemm<<<dim3(NT,1), blk>>>(h, Wb,  0, Wbs,  nullptr, nullptr, nullptr, nullptr, nullptr, nullptr, 1, Bsz);
    tile_gemm<<<dim3(NT,1), blk>>>(h, Whh, 0, hWhh, nullptr, nullptr, nullptr, nullptr, nullptr, nullptr, 1, Bsz);

    // Fused score GEMMs (the big work): partial[nt, b*T+t] = sum_j V[j]*tanh((F@W)+Uh+b)
    tile_gemm<<<dim3(NT, (Bsz*TVv)/TM), blk>>>(F,  Wav, 1, nullptr, nullptr, nullptr, Uhv, bav, Vav, pv, TVv, Bsz*TVv);
    tile_gemm<<<dim3(NT, (Bsz*TTt)/TM), blk>>>(Tx, Wat, 1, nullptr, nullptr, nullptr, Uht, bat, Vat, pt, TTt, Bsz*TTt);

    // Softmax over time
    softmax_k<<<Bsz, 256>>>(pv, av, TVv, Bsz*TVv);
    softmax_k<<<Bsz, 256>>>(pt, at, TTt, Bsz*TTt);

    // Attention-weighted sums
    wsum_k<<<dim3(Bsz, Hd/128), 128>>>(F,  av, hv, TVv);
    wsum_k<<<dim3(Bsz, Hd/128), 128>>>(Tx, at, ht, TTt);

    // Encoders and gate pre-activations
    tile_gemm<<<dim3(NT,1), blk>>>(hv, WveT, 0, hv2, bve, nullptr, nullptr, nullptr, nullptr, nullptr, 1, Bsz);
    tile_gemm<<<dim3(NT,1), blk>>>(ht, WqeT, 0, ht2, bqe, nullptr, nullptr, nullptr, nullptr, nullptr, 1, Bsz);
    tile_gemm<<<dim3(NT,1), blk>>>(hv, Vbv,  0, mv1, bbv, Wbs,     nullptr, nullptr, nullptr, nullptr, 1, Bsz);
    tile_gemm<<<dim3(NT,1), blk>>>(ht, Vbt,  0, mt1, bbt, Wbs,     nullptr, nullptr, nullptr, nullptr, 1, Bsz);

    // Gate + output
    logits_k<<<2*Bsz, 128>>>(mv1, mt1, wb, lg);
    beta_k<<<1, 128>>>(lg, beta);
    final_k<<<Bsz, Hd>>>(hWhh, hv2, ht2, bh, beta, out);
}

// round 9
// speedup vs baseline: 8.5296x; 8.5296x over previous
#include <cuda_runtime.h>
#include <cuda_bf16.h>
#include <cstdint>
#include <cstddef>

#define Bsz 64
#define Hd  512
#define TVv 512
#define TTt 64
#define NS  8          // partial slices for score reduction (4 n-CTAs x 2 n-warps)

typedef unsigned long long ull;

// ---------------- device scratch (no runtime allocation allowed) ----------------
__device__ __nv_bfloat16 g_Fb  [Bsz*TVv*Hd];   // bf16 copy of hidden_frames
__device__ __nv_bfloat16 g_Tb  [Bsz*TTt*Hd];   // bf16 copy of hidden_text
__device__ __nv_bfloat16 g_Wavb[Hd*Hd];
__device__ __nv_bfloat16 g_Watb[Hd*Hd];

__device__ float g_Uhv [Bsz*Hd];
__device__ float g_Uht [Bsz*Hd];
__device__ float g_Wbs [Bsz*Hd];
__device__ float g_hWhh[Bsz*Hd];
__device__ float g_part_v[NS*Bsz*TVv];
__device__ float g_part_t[NS*Bsz*TTt];
__device__ float g_av [Bsz*TVv];
__device__ float g_at [Bsz*TTt];
__device__ float g_hv [Bsz*Hd];
__device__ float g_ht [Bsz*Hd];
__device__ float g_hv2[Bsz*Hd];
__device__ float g_ht2[Bsz*Hd];
__device__ float g_mv1[Bsz*Hd];
__device__ float g_mt1[Bsz*Hd];
__device__ float g_logits[2*Bsz];
__device__ float g_beta[2];

// ---------------- small helpers ----------------
__device__ __forceinline__ uint32_t pack_bf16(float lo, float hi) {
    uint32_t r;
    asm("cvt.rn.bf16x2.f32 %0, %1, %2;" : "=r"(r) : "f"(hi), "f"(lo));
    return r;
}
__device__ __forceinline__ uint32_t s2u(const void* p) {
    return (uint32_t)__cvta_generic_to_shared(p);
}
__device__ __forceinline__ void cp16(uint32_t dst, const void* src) {
    asm volatile("cp.async.cg.shared.global [%0], [%1], 16;" :: "r"(dst), "l"(src));
}
__device__ __forceinline__ float tanh_fast(float x) {
    float y; asm("tanh.approx.f32 %0, %1;" : "=f"(y) : "f"(x)); return y;
}
__device__ __forceinline__ ull dup2(float x) {
    ull r; unsigned u = __float_as_uint(x);
    asm("mov.b64 %0, {%1, %1};" : "=l"(r) : "r"(u));
    return r;
}
__device__ __forceinline__ void fma2(ull &d, ull a, ull b) {
    asm("fma.rn.f32x2 %0, %1, %2, %3;" : "=l"(d) : "l"(a), "l"(b), "l"(d));
}
__device__ __forceinline__ float2 u2f(ull v) {
    float2 f;
    f.x = __uint_as_float((unsigned)(v & 0xffffffffu));
    f.y = __uint_as_float((unsigned)(v >> 32));
    return f;
}
__device__ __forceinline__ uint32_t ldb2(const __nv_bfloat16* bs, int i0, int i1) {
    uint32_t lo = *(const unsigned short*)(bs + i0);
    uint32_t hi = *(const unsigned short*)(bs + i1);
    return lo | (hi << 16);
}
__device__ __forceinline__ void mma_bf16(float* c, const uint32_t* a, uint32_t b0, uint32_t b1) {
    asm volatile(
        "mma.sync.aligned.m16n8k16.row.col.f32.bf16.bf16.f32 "
        "{%0,%1,%2,%3}, {%4,%5,%6,%7}, {%8,%9}, {%0,%1,%2,%3};"
        : "+f"(c[0]), "+f"(c[1]), "+f"(c[2]), "+f"(c[3])
        : "r"(a[0]), "r"(a[1]), "r"(a[2]), "r"(a[3]), "r"(b0), "r"(b1));
}

// ---------------- fp32 -> bf16 conversion (8 elems / thread) ----------------
__global__ void cvt_bf16_k(const float* __restrict__ src, __nv_bfloat16* __restrict__ dst) {
    size_t i = ((size_t)blockIdx.x * 256 + threadIdx.x) * 8;
    float4 v0 = *(const float4*)(src + i);
    float4 v1 = *(const float4*)(src + i + 4);
    uint4 o;
    o.x = pack_bf16(v0.x, v0.y); o.y = pack_bf16(v0.z, v0.w);
    o.z = pack_bf16(v1.x, v1.y); o.w = pack_bf16(v1.z, v1.w);
    *(uint4*)(dst + i) = o;
}

// ---------------- bf16 tensor-core score kernel ----------------
// partial[slice*R + row] = sum_{j in 64-col slice} V[j]*tanh((A@W)[row,j] + Uh[b,j] + sbias[j])
// CTA: 128 rows x 128 cols, K=512 in 16 chunks of 32. 8 warps = 4(m) x 2(n).
#define ASTR 40
#define BSTR 136

__device__ __forceinline__ void score_issue(const __nv_bfloat16* Ag, const __nv_bfloat16* W,
                                            int n0, int c, __nv_bfloat16* as, __nv_bfloat16* bs, int tid)
{
#pragma unroll
    for (int i = 0; i < 2; i++) {           // A: 128 rows x 32 bf16
        int e = tid + i * 256;
        int r = e >> 2, seg = e & 3;
        cp16(s2u(as + r * ASTR + seg * 8), Ag + (size_t)r * Hd + c * 32 + seg * 8);
    }
#pragma unroll
    for (int i = 0; i < 2; i++) {           // B: 32 k-rows x 128 bf16
        int e = tid + i * 256;
        int k = e >> 4, seg = e & 15;
        cp16(s2u(bs + k * BSTR + seg * 8), W + (size_t)(c * 32 + k) * Hd + n0 + seg * 8);
    }
    asm volatile("cp.async.commit_group;" ::: "memory");
}

__global__ void __launch_bounds__(256, 2)
score_mma(const __nv_bfloat16* __restrict__ A, const __nv_bfloat16* __restrict__ W,
          const float* __restrict__ Uh, const float* __restrict__ sbias,
          const float* __restrict__ V, float* __restrict__ partial, int T, int R)
{
    __shared__ __align__(16) __nv_bfloat16 As[2][128 * ASTR];
    __shared__ __align__(16) __nv_bfloat16 Bs[2][32 * BSTR];

    const int tid  = threadIdx.x;
    const int lane = tid & 31, wid = tid >> 5;
    const int wm = wid & 3, wn = wid >> 2;
    const int gid = lane >> 2, tig = lane & 3;
    const int n0 = blockIdx.x * 128;
    const int m0 = blockIdx.y * 128;
    const __nv_bfloat16* Ag = A + (size_t)m0 * Hd;

    float acc[2][8][4];
#pragma unroll
    for (int a = 0; a < 2; a++)
#pragma unroll
        for (int b = 0; b < 8; b++)
#pragma unroll
            for (int c = 0; c < 4; c++) acc[a][b][c] = 0.f;

    score_issue(Ag, W, n0, 0, As[0], Bs[0], tid);

#pragma unroll 1
    for (int c = 0; c < 16; c++) {
        if (c + 1 < 16) {
            score_issue(Ag, W, n0, c + 1, As[(c + 1) & 1], Bs[(c + 1) & 1], tid);
            asm volatile("cp.async.wait_group 1;" ::: "memory");
        } else {
            asm volatile("cp.async.wait_group 0;" ::: "memory");
        }
        __syncthreads();
        const __nv_bfloat16* as = As[c & 1];
        const __nv_bfloat16* bs = Bs[c & 1];
#pragma unroll
        for (int kf = 0; kf < 2; kf++) {
            const int kb = kf * 16;
            const int c0 = kb + tig * 2;
            uint32_t af[2][4];
#pragma unroll
            for (int mf = 0; mf < 2; mf++) {
                int r = wm * 32 + mf * 16 + gid;
                af[mf][0] = *(const uint32_t*)(as + r * ASTR + c0);
                af[mf][1] = *(const uint32_t*)(as + (r + 8) * ASTR + c0);
                af[mf][2] = *(const uint32_t*)(as + r * ASTR + c0 + 8);
                af[mf][3] = *(const uint32_t*)(as + (r + 8) * ASTR + c0 + 8);
            }
#pragma unroll
            for (int nf = 0; nf < 8; nf++) {
                int n  = wn * 64 + nf * 8 + gid;
                int k0 = kb + tig * 2;
                uint32_t b0 = ldb2(bs, k0 * BSTR + n, (k0 + 1) * BSTR + n);
                uint32_t b1 = ldb2(bs, (k0 + 8) * BSTR + n, (k0 + 9) * BSTR + n);
                mma_bf16(acc[0][nf], af[0], b0, b1);
                mma_bf16(acc[1][nf], af[1], b0, b1);
            }
        }
        __syncthreads();
    }

    // Fused epilogue: tanh + dot with V, reduce over this warp's 64-col slice
    const int base_m = m0 + wm * 32;
    float s[2][2];
#pragma unroll
    for (int mf = 0; mf < 2; mf++) {
#pragma unroll
        for (int h = 0; h < 2; h++) {
            int row = base_m + mf * 16 + h * 8 + gid;
            int b = row / T;
            const float* UhR = Uh + (size_t)b * Hd;
            float ss = 0.f;
#pragma unroll
            for (int nf = 0; nf < 8; nf++) {
#pragma unroll
                for (int e = 0; e < 2; e++) {
                    int col = n0 + wn * 64 + nf * 8 + tig * 2 + e;
                    float x = acc[mf][nf][h * 2 + e] + UhR[col] + sbias[col];
                    ss += V[col] * tanh_fast(x);
                }
            }
            s[mf][h] = ss;
        }
    }
#pragma unroll
    for (int mf = 0; mf < 2; mf++)
#pragma unroll
        for (int h = 0; h < 2; h++) {
            s[mf][h] += __shfl_xor_sync(0xffffffffu, s[mf][h], 1);
            s[mf][h] += __shfl_xor_sync(0xffffffffu, s[mf][h], 2);
        }
    if (tig == 0) {
        const int slice = blockIdx.x * 2 + wn;
#pragma unroll
        for (int mf = 0; mf < 2; mf++)
#pragma unroll
            for (int h = 0; h < 2; h++)
                partial[(size_t)slice * R + base_m + mf * 16 + h * 8 + gid] = s[mf][h];
    }
}

// ---------------- fused skinny GEMMs: 4 gemms per launch ----------------
// C = A[64,512] @ (W or W^T)[512,512] (+bias)(+addmat). Grid (8 col-tiles, 4 gemms).
struct GDesc { const float* A; const float* W; float* C; const float* bias; const float* add; int trans; };
struct GDesc4 { GDesc g[4]; };

__global__ void __launch_bounds__(256, 4)
sgemm4(GDesc4 ds) {
    const GDesc d = ds.g[blockIdx.y];
    const int n0 = blockIdx.x * 64;
    __shared__ float Asm[32][68];  // [k][m]
    __shared__ float Bsm[32][68];  // [k][n]
    const int tid = threadIdx.x;
    const int tx = tid & 15, ty = tid >> 4;

    ull c2[4][2];
#pragma unroll
    for (int i = 0; i < 4; i++) { c2[i][0] = 0ull; c2[i][1] = 0ull; }

    for (int kt = 0; kt < Hd; kt += 32) {
        __syncthreads();
#pragma unroll
        for (int i = 0; i < 2; i++) {   // A: 64 rows x 32 k
            int f = tid + i * 256;
            int m = f >> 3, ko = (f & 7) * 4;
            float4 v = *(const float4*)(d.A + (size_t)m * Hd + kt + ko);
            Asm[ko][m] = v.x; Asm[ko + 1][m] = v.y; Asm[ko + 2][m] = v.z; Asm[ko + 3][m] = v.w;
        }
        if (!d.trans) {
#pragma unroll
            for (int i = 0; i < 2; i++) {
                int f = tid + i * 256;
                int k = f >> 4, nn = (f & 15) * 4;
                float4 v = *(const float4*)(d.W + (size_t)(kt + k) * Hd + n0 + nn);
                *(float4*)&Bsm[k][nn] = v;
            }
        } else {
#pragma unroll
            for (int i = 0; i < 2; i++) {
                int f = tid + i * 256;
                int nn = f >> 3, ko = (f & 7) * 4;
                float4 v = *(const float4*)(d.W + (size_t)(n0 + nn) * Hd + kt + ko);
                Bsm[ko][nn] = v.x; Bsm[ko + 1][nn] = v.y; Bsm[ko + 2][nn] = v.z; Bsm[ko + 3][nn] = v.w;
            }
        }
        __syncthreads();
#pragma unroll
        for (int k = 0; k < 32; k++) {
            float4 a = *(const float4*)&Asm[k][ty * 4];
            const ull* bp = (const ull*)&Bsm[k][tx * 4];
            ull b0 = bp[0], b1 = bp[1];
            ull a0 = dup2(a.x), a1 = dup2(a.y), a2 = dup2(a.z), a3 = dup2(a.w);
            fma2(c2[0][0], a0, b0); fma2(c2[0][1], a0, b1);
            fma2(c2[1][0], a1, b0); fma2(c2[1][1], a1, b1);
            fma2(c2[2][0], a2, b0); fma2(c2[2][1], a2, b1);
            fma2(c2[3][0], a3, b0); fma2(c2[3][1], a3, b1);
        }
    }
#pragma unroll
    for (int i = 0; i < 4; i++) {
        int m = ty * 4 + i;
#pragma unroll
        for (int p = 0; p < 2; p++) {
            float2 v = u2f(c2[i][p]);
            int col = n0 + tx * 4 + p * 2;
            float x0 = v.x, x1 = v.y;
            if (d.bias) { x0 += d.bias[col];                  x1 += d.bias[col + 1]; }
            if (d.add)  { x0 += d.add[(size_t)m * Hd + col];  x1 += d.add[(size_t)m * Hd + col + 1]; }
            d.C[(size_t)m * Hd + col] = x0;
            d.C[(size_t)m * Hd + col + 1] = x1;
        }
    }
}

// ---------------- softmax over T per batch (sums NS partial slices) ----------------
__global__ void softmax_k(const float* __restrict__ part, float* __restrict__ out, int T, int R) {
    __shared__ float buf[TVv];
    __shared__ float red[256];
    const int b = blockIdx.x, tid = threadIdx.x;
    for (int t = tid; t < T; t += 256) {
        float s = 0.f;
#pragma unroll
        for (int n = 0; n < NS; n++) s += part[(size_t)n * R + b * T + t];
        buf[t] = s;
    }
    __syncthreads();
    float m = -1e30f;
    for (int t = tid; t < T; t += 256) m = fmaxf(m, buf[t]);
    red[tid] = m; __syncthreads();
    for (int o = 128; o > 0; o >>= 1) { if (tid < o) red[tid] = fmaxf(red[tid], red[tid + o]); __syncthreads(); }
    m = red[0]; __syncthreads();
    float s = 0.f;
    for (int t = tid; t < T; t += 256) { float e = expf(buf[t] - m); buf[t] = e; s += e; }
    red[tid] = s; __syncthreads();
    for (int o = 128; o > 0; o >>= 1) { if (tid < o) red[tid] += red[tid + o]; __syncthreads(); }
    float inv = 1.f / red[0];
    for (int t = tid; t < T; t += 256) out[b * T + t] = buf[t] * inv;
}

// ---------------- weighted sum: out[b,:] = a[b,:] @ F[b,:,:] ----------------
__global__ void wsum_k(const float* __restrict__ F, const float* __restrict__ a,
                       float* __restrict__ out, int T) {
    __shared__ float as_[TVv];
    const int b = blockIdx.x;
    const int j = blockIdx.y * 128 + threadIdx.x;
    for (int t = threadIdx.x; t < T; t += 128) as_[t] = a[b * T + t];
    __syncthreads();
    const float* Fb = F + (size_t)b * T * Hd + j;
    float acc = 0.f;
#pragma unroll 8
    for (int t = 0; t < T; t++) acc += as_[t] * Fb[(size_t)t * Hd];
    out[b * Hd + j] = acc;
}

// ---------------- gating logits ----------------
__global__ void logits_k(const float* __restrict__ mv1, const float* __restrict__ mt1,
                         const float* __restrict__ wb, float* __restrict__ lg) {
    __shared__ float red[128];
    const int r = blockIdx.x, tid = threadIdx.x;
    const float* row = (r < Bsz) ? (mv1 + (size_t)r * Hd) : (mt1 + (size_t)(r - Bsz) * Hd);
    float s = 0.f;
    for (int k = tid; k < Hd; k += 128) s += tanhf(row[k]) * wb[k];
    red[tid] = s; __syncthreads();
    for (int o = 64; o > 0; o >>= 1) { if (tid < o) red[tid] += red[tid + o]; __syncthreads(); }
    if (tid == 0) lg[r] = red[0];
}

__global__ void beta_k(const float* __restrict__ lg, float* __restrict__ beta) {
    __shared__ float red[128];
    __shared__ float ev[128];
    const int tid = threadIdx.x;
    float l = lg[tid];
    red[tid] = l; __syncthreads();
    for (int o = 64; o > 0; o >>= 1) { if (tid < o) red[tid] = fmaxf(red[tid], red[tid + o]); __syncthreads(); }
    float m = red[0]; __syncthreads();
    float e = expf(l - m);
    ev[tid] = e; red[tid] = e; __syncthreads();
    for (int o = 64; o > 0; o >>= 1) { if (tid < o) red[tid] += red[tid + o]; __syncthreads(); }
    if (tid == 0) { beta[0] = ev[0] / red[0]; beta[1] = ev[1] / red[0]; }
}

__global__ void final_k(const float* __restrict__ hWhh, const float* __restrict__ hv2,
                        const float* __restrict__ ht2, const float* __restrict__ bh,
                        const float* __restrict__ beta, float* __restrict__ out) {
    const int idx = blockIdx.x * blockDim.x + threadIdx.x;
    out[idx] = tanhf(hWhh[idx] + beta[0] * hv2[idx] + beta[1] * ht2[idx] + bh[idx & (Hd - 1)]);
}

// ---------------- host launcher ----------------
extern "C" void kernel_launch(void* const* d_in, const int* in_sizes, int n_in,
                              void* d_out, int out_size) {
    const float* h   = (const float*)d_in[0];
    const float* F   = (const float*)d_in[1];
    const float* Tx  = (const float*)d_in[2];
    const float* Wav = (const float*)d_in[3];
    const float* Wat = (const float*)d_in[4];
    const float* Uav = (const float*)d_in[5];
    const float* Uat = (const float*)d_in[6];
    const float* Vav = (const float*)d_in[7];
    const float* Vat = (const float*)d_in[8];
    const float* bav = (const float*)d_in[9];
    const float* bat = (const float*)d_in[10];
    const float* Whh = (const float*)d_in[11];
    const float* bh  = (const float*)d_in[12];
    const float* Wve = (const float*)d_in[13];
    const float* bve = (const float*)d_in[14];
    const float* Wqe = (const float*)d_in[15];
    const float* bqe = (const float*)d_in[16];
    const float* Wb  = (const float*)d_in[17];
    const float* Vbv = (const float*)d_in[18];
    const float* Vbt = (const float*)d_in[19];
    const float* bbv = (const float*)d_in[20];
    const float* bbt = (const float*)d_in[21];
    const float* wb  = (const float*)d_in[22];
    float* out = (float*)d_out;

    __nv_bfloat16 *Fb, *Tb, *Wavb, *Watb;
    float *Uhv, *Uht, *Wbs, *hWhh, *pv, *pt, *av, *at,
          *hv, *ht, *hv2, *ht2, *mv1, *mt1, *lg, *beta;
    cudaGetSymbolAddress((void**)&Fb,   g_Fb);
    cudaGetSymbolAddress((void**)&Tb,   g_Tb);
    cudaGetSymbolAddress((void**)&Wavb, g_Wavb);
    cudaGetSymbolAddress((void**)&Watb, g_Watb);
    cudaGetSymbolAddress((void**)&Uhv,  g_Uhv);
    cudaGetSymbolAddress((void**)&Uht,  g_Uht);
    cudaGetSymbolAddress((void**)&Wbs,  g_Wbs);
    cudaGetSymbolAddress((void**)&hWhh, g_hWhh);
    cudaGetSymbolAddress((void**)&pv,   g_part_v);
    cudaGetSymbolAddress((void**)&pt,   g_part_t);
    cudaGetSymbolAddress((void**)&av,   g_av);
    cudaGetSymbolAddress((void**)&at,   g_at);
    cudaGetSymbolAddress((void**)&hv,   g_hv);
    cudaGetSymbolAddress((void**)&ht,   g_ht);
    cudaGetSymbolAddress((void**)&hv2,  g_hv2);
    cudaGetSymbolAddress((void**)&ht2,  g_ht2);
    cudaGetSymbolAddress((void**)&mv1,  g_mv1);
    cudaGetSymbolAddress((void**)&mt1,  g_mt1);
    cudaGetSymbolAddress((void**)&lg,   g_logits);
    cudaGetSymbolAddress((void**)&beta, g_beta);

    // bf16 conversions (independent; run first)
    cvt_bf16_k<<<(Bsz*TVv*Hd)/2048, 256>>>(F,   Fb);
    cvt_bf16_k<<<(Bsz*TTt*Hd)/2048, 256>>>(Tx,  Tb);
    cvt_bf16_k<<<(Hd*Hd)/2048,      256>>>(Wav, Wavb);
    cvt_bf16_k<<<(Hd*Hd)/2048,      256>>>(Wat, Watb);

    // Conditioning GEMMs: h @ {Uav, Uat, Wb, Whh} in one launch
    GDesc4 p1;
    p1.g[0] = { h, Uav, Uhv,  nullptr, nullptr, 0 };
    p1.g[1] = { h, Uat, Uht,  nullptr, nullptr, 0 };
    p1.g[2] = { h, Wb,  Wbs,  nullptr, nullptr, 0 };
    p1.g[3] = { h, Whh, hWhh, nullptr, nullptr, 0 };
    sgemm4<<<dim3(8, 4), 256>>>(p1);

    // Tensor-core fused score GEMMs
    score_mma<<<dim3(4, (Bsz*TVv)/128), 256>>>(Fb, Wavb, Uhv, bav, Vav, pv, TVv, Bsz*TVv);
    score_mma<<<dim3(4, (Bsz*TTt)/128), 256>>>(Tb, Watb, Uht, bat, Vat, pt, TTt, Bsz*TTt);

    // Softmax over time
    softmax_k<<<Bsz, 256>>>(pv, av, TVv, Bsz*TVv);
    softmax_k<<<Bsz, 256>>>(pt, at, TTt, Bsz*TTt);

    // Attention-weighted sums
    wsum_k<<<dim3(Bsz, Hd/128), 128>>>(F,  av, hv, TVv);
    wsum_k<<<dim3(Bsz, Hd/128), 128>>>(Tx, at, ht, TTt);

    // Encoders + gate pre-activations in one launch (trans handles the .T)
    GDesc4 p2;
    p2.g[0] = { hv, Wve, hv2, bve, nullptr, 1 };
    p2.g[1] = { ht, Wqe, ht2, bqe, nullptr, 1 };
    p2.g[2] = { hv, Vbv, mv1, bbv, Wbs,     0 };
    p2.g[3] = { ht, Vbt, mt1, bbt, Wbs,     0 };
    sgemm4<<<dim3(8, 4), 256>>>(p2);

    // Gate + output
    logits_k<<<2*Bsz, 128>>>(mv1, mt1, wb, lg);
    beta_k<<<1, 128>>>(lg, beta);
    final_k<<<Bsz, Hd>>>(hWhh, hv2, ht2, bh, beta, out);
}

// round 10
// speedup vs baseline: 8.9958x; 1.0547x over previous
#include <cuda_runtime.h>
#include <cuda_bf16.h>
#include <cstdint>
#include <cstddef>

#define Bsz 64
#define Hd  512
#define TVv 512
#define TTt 64
#define NS  8          // partial slices for score reduction (4 n-CTAs x 2 n-warps)

typedef unsigned long long ull;

// ---------------- device scratch (no runtime allocation allowed) ----------------
__device__ __nv_bfloat16 g_Fb  [Bsz*TVv*Hd];   // bf16 copy of hidden_frames
__device__ __nv_bfloat16 g_Tb  [Bsz*TTt*Hd];   // bf16 copy of hidden_text
__device__ __nv_bfloat16 g_WavT[Hd*Hd];        // bf16 transposed Wav  [n][k]
__device__ __nv_bfloat16 g_WatT[Hd*Hd];        // bf16 transposed Wat  [n][k]

__device__ float g_Uhv [Bsz*Hd];
__device__ float g_Uht [Bsz*Hd];
__device__ float g_Wbs [Bsz*Hd];
__device__ float g_hWhh[Bsz*Hd];
__device__ float g_part_v[NS*Bsz*TVv];
__device__ float g_part_t[NS*Bsz*TTt];
__device__ float g_av [Bsz*TVv];
__device__ float g_at [Bsz*TTt];
__device__ float g_hv [Bsz*Hd];
__device__ float g_ht [Bsz*Hd];
__device__ float g_hv2[Bsz*Hd];
__device__ float g_ht2[Bsz*Hd];
__device__ float g_mv1[Bsz*Hd];
__device__ float g_mt1[Bsz*Hd];
__device__ float g_logits[2*Bsz];
__device__ float g_beta[2];

// ---------------- small helpers ----------------
__device__ __forceinline__ uint32_t pack_bf16(float lo, float hi) {
    uint32_t r;
    asm("cvt.rn.bf16x2.f32 %0, %1, %2;" : "=r"(r) : "f"(hi), "f"(lo));
    return r;
}
__device__ __forceinline__ uint32_t s2u(const void* p) {
    return (uint32_t)__cvta_generic_to_shared(p);
}
__device__ __forceinline__ void cp16(uint32_t dst, const void* src) {
    asm volatile("cp.async.cg.shared.global [%0], [%1], 16;" :: "r"(dst), "l"(src));
}
__device__ __forceinline__ float tanh_fast(float x) {
    float y; asm("tanh.approx.f32 %0, %1;" : "=f"(y) : "f"(x)); return y;
}
__device__ __forceinline__ ull dup2(float x) {
    ull r; unsigned u = __float_as_uint(x);
    asm("mov.b64 %0, {%1, %1};" : "=l"(r) : "r"(u));
    return r;
}
__device__ __forceinline__ void fma2(ull &d, ull a, ull b) {
    asm("fma.rn.f32x2 %0, %1, %2, %3;" : "=l"(d) : "l"(a), "l"(b), "l"(d));
}
__device__ __forceinline__ float2 u2f(ull v) {
    float2 f;
    f.x = __uint_as_float((unsigned)(v & 0xffffffffu));
    f.y = __uint_as_float((unsigned)(v >> 32));
    return f;
}
__device__ __forceinline__ void mma_bf16(float* c, const uint32_t* a, uint32_t b0, uint32_t b1) {
    asm volatile(
        "mma.sync.aligned.m16n8k16.row.col.f32.bf16.bf16.f32 "
        "{%0,%1,%2,%3}, {%4,%5,%6,%7}, {%8,%9}, {%0,%1,%2,%3};"
        : "+f"(c[0]), "+f"(c[1]), "+f"(c[2]), "+f"(c[3])
        : "r"(a[0]), "r"(a[1]), "r"(a[2]), "r"(a[3]), "r"(b0), "r"(b1));
}

// ---------------- fp32 -> bf16 conversion (8 elems / thread) ----------------
__global__ void cvt_bf16_k(const float* __restrict__ src, __nv_bfloat16* __restrict__ dst) {
    size_t i = ((size_t)blockIdx.x * 256 + threadIdx.x) * 8;
    float4 v0 = *(const float4*)(src + i);
    float4 v1 = *(const float4*)(src + i + 4);
    uint4 o;
    o.x = pack_bf16(v0.x, v0.y); o.y = pack_bf16(v0.z, v0.w);
    o.z = pack_bf16(v1.x, v1.y); o.w = pack_bf16(v1.z, v1.w);
    *(uint4*)(dst + i) = o;
}

// ---------------- fp32 W[k][n] -> bf16 W^T[n][k] ----------------
__global__ void cvt_wt_k(const float* __restrict__ in, __nv_bfloat16* __restrict__ out) {
    __shared__ float tile[32][33];
    int x  = blockIdx.x * 32 + threadIdx.x;
    int y0 = blockIdx.y * 32;
#pragma unroll
    for (int i = threadIdx.y; i < 32; i += 8)
        tile[i][threadIdx.x] = in[(size_t)(y0 + i) * Hd + x];
    __syncthreads();
    int k   = y0 + threadIdx.x;
    int nb0 = blockIdx.x * 32;
#pragma unroll
    for (int i = threadIdx.y; i < 32; i += 8)
        out[(size_t)(nb0 + i) * Hd + k] = __float2bfloat16(tile[threadIdx.x][i]);
}

// ---------------- bf16 tensor-core score kernel ----------------
// partial[slice*R + row] = sum_{j in 64-col slice} V[j]*tanh((A@W)[row,j] + Uh[b,j] + sbias[j])
// CTA: 128 rows x 128 cols, K=512 in 16 chunks of 32. 8 warps = 4(m) x 2(n).
// Both A and B(=W^T) tiles are k-contiguous rows with stride 40 (conflict-free).
#define ASTR 40

__device__ __forceinline__ void score_issue(const __nv_bfloat16* Ag, const __nv_bfloat16* WT,
                                            int n0, int c, __nv_bfloat16* as, __nv_bfloat16* bs, int tid)
{
#pragma unroll
    for (int i = 0; i < 2; i++) {           // A: 128 rows x 32 bf16
        int e = tid + i * 256;
        int r = e >> 2, seg = e & 3;
        cp16(s2u(as + r * ASTR + seg * 8), Ag + (size_t)r * Hd + c * 32 + seg * 8);
    }
#pragma unroll
    for (int i = 0; i < 2; i++) {           // B: 128 n-rows x 32 k bf16
        int e = tid + i * 256;
        int r = e >> 2, seg = e & 3;
        cp16(s2u(bs + r * ASTR + seg * 8), WT + (size_t)(n0 + r) * Hd + c * 32 + seg * 8);
    }
    asm volatile("cp.async.commit_group;" ::: "memory");
}

__global__ void __launch_bounds__(256, 2)
score_mma(const __nv_bfloat16* __restrict__ A, const __nv_bfloat16* __restrict__ WT,
          const float* __restrict__ Uh, const float* __restrict__ sbias,
          const float* __restrict__ V, float* __restrict__ partial, int T, int R)
{
    __shared__ __align__(16) __nv_bfloat16 As[2][128 * ASTR];
    __shared__ __align__(16) __nv_bfloat16 Bs[2][128 * ASTR];

    const int tid  = threadIdx.x;
    const int lane = tid & 31, wid = tid >> 5;
    const int wm = wid & 3, wn = wid >> 2;
    const int gid = lane >> 2, tig = lane & 3;
    const int n0 = blockIdx.x * 128;
    const int m0 = blockIdx.y * 128;
    const __nv_bfloat16* Ag = A + (size_t)m0 * Hd;

    float acc[2][8][4];
#pragma unroll
    for (int a = 0; a < 2; a++)
#pragma unroll
        for (int b = 0; b < 8; b++)
#pragma unroll
            for (int c = 0; c < 4; c++) acc[a][b][c] = 0.f;

    score_issue(Ag, WT, n0, 0, As[0], Bs[0], tid);

#pragma unroll 1
    for (int c = 0; c < 16; c++) {
        if (c + 1 < 16) {
            score_issue(Ag, WT, n0, c + 1, As[(c + 1) & 1], Bs[(c + 1) & 1], tid);
            asm volatile("cp.async.wait_group 1;" ::: "memory");
        } else {
            asm volatile("cp.async.wait_group 0;" ::: "memory");
        }
        __syncthreads();
        const __nv_bfloat16* as = As[c & 1];
        const __nv_bfloat16* bs = Bs[c & 1];
#pragma unroll
        for (int kf = 0; kf < 2; kf++) {
            const int c0 = kf * 16 + tig * 2;
            uint32_t af[2][4];
#pragma unroll
            for (int mf = 0; mf < 2; mf++) {
                int r = wm * 32 + mf * 16 + gid;
                af[mf][0] = *(const uint32_t*)(as + r * ASTR + c0);
                af[mf][1] = *(const uint32_t*)(as + (r + 8) * ASTR + c0);
                af[mf][2] = *(const uint32_t*)(as + r * ASTR + c0 + 8);
                af[mf][3] = *(const uint32_t*)(as + (r + 8) * ASTR + c0 + 8);
            }
#pragma unroll
            for (int nf = 0; nf < 8; nf++) {
                int n = wn * 64 + nf * 8 + gid;
                uint32_t b0 = *(const uint32_t*)(bs + n * ASTR + c0);
                uint32_t b1 = *(const uint32_t*)(bs + n * ASTR + c0 + 8);
                mma_bf16(acc[0][nf], af[0], b0, b1);
                mma_bf16(acc[1][nf], af[1], b0, b1);
            }
        }
        __syncthreads();
    }

    // Fused epilogue: tanh + dot with V, reduce over this warp's 64-col slice
    const int base_m = m0 + wm * 32;
    float s[2][2];
#pragma unroll
    for (int mf = 0; mf < 2; mf++) {
#pragma unroll
        for (int h = 0; h < 2; h++) {
            int row = base_m + mf * 16 + h * 8 + gid;
            int b = row / T;
            const float* UhR = Uh + (size_t)b * Hd;
            float ss = 0.f;
#pragma unroll
            for (int nf = 0; nf < 8; nf++) {
#pragma unroll
                for (int e = 0; e < 2; e++) {
                    int col = n0 + wn * 64 + nf * 8 + tig * 2 + e;
                    float x = acc[mf][nf][h * 2 + e] + UhR[col] + sbias[col];
                    ss += V[col] * tanh_fast(x);
                }
            }
            s[mf][h] = ss;
        }
    }
#pragma unroll
    for (int mf = 0; mf < 2; mf++)
#pragma unroll
        for (int h = 0; h < 2; h++) {
            s[mf][h] += __shfl_xor_sync(0xffffffffu, s[mf][h], 1);
            s[mf][h] += __shfl_xor_sync(0xffffffffu, s[mf][h], 2);
        }
    if (tig == 0) {
        const int slice = blockIdx.x * 2 + wn;
#pragma unroll
        for (int mf = 0; mf < 2; mf++)
#pragma unroll
            for (int h = 0; h < 2; h++)
                partial[(size_t)slice * R + base_m + mf * 16 + h * 8 + gid] = s[mf][h];
    }
}

// ---------------- fused skinny GEMMs: 4 gemms per launch ----------------
struct GDesc { const float* A; const float* W; float* C; const float* bias; const float* add; int trans; };
struct GDesc4 { GDesc g[4]; };

__global__ void __launch_bounds__(256, 4)
sgemm4(GDesc4 ds) {
    const GDesc d = ds.g[blockIdx.y];
    const int n0 = blockIdx.x * 64;
    __shared__ float Asm[32][68];  // [k][m]
    __shared__ float Bsm[32][68];  // [k][n]
    const int tid = threadIdx.x;
    const int tx = tid & 15, ty = tid >> 4;

    ull c2[4][2];
#pragma unroll
    for (int i = 0; i < 4; i++) { c2[i][0] = 0ull; c2[i][1] = 0ull; }

    for (int kt = 0; kt < Hd; kt += 32) {
        __syncthreads();
#pragma unroll
        for (int i = 0; i < 2; i++) {   // A: 64 rows x 32 k
            int f = tid + i * 256;
            int m = f >> 3, ko = (f & 7) * 4;
            float4 v = *(const float4*)(d.A + (size_t)m * Hd + kt + ko);
            Asm[ko][m] = v.x; Asm[ko + 1][m] = v.y; Asm[ko + 2][m] = v.z; Asm[ko + 3][m] = v.w;
        }
        if (!d.trans) {
#pragma unroll
            for (int i = 0; i < 2; i++) {
                int f = tid + i * 256;
                int k = f >> 4, nn = (f & 15) * 4;
                float4 v = *(const float4*)(d.W + (size_t)(kt + k) * Hd + n0 + nn);
                *(float4*)&Bsm[k][nn] = v;
            }
        } else {
#pragma unroll
            for (int i = 0; i < 2; i++) {
                int f = tid + i * 256;
                int nn = f >> 3, ko = (f & 7) * 4;
                float4 v = *(const float4*)(d.W + (size_t)(n0 + nn) * Hd + kt + ko);
                Bsm[ko][nn] = v.x; Bsm[ko + 1][nn] = v.y; Bsm[ko + 2][nn] = v.z; Bsm[ko + 3][nn] = v.w;
            }
        }
        __syncthreads();
#pragma unroll
        for (int k = 0; k < 32; k++) {
            float4 a = *(const float4*)&Asm[k][ty * 4];
            const ull* bp = (const ull*)&Bsm[k][tx * 4];
            ull b0 = bp[0], b1 = bp[1];
            ull a0 = dup2(a.x), a1 = dup2(a.y), a2 = dup2(a.z), a3 = dup2(a.w);
            fma2(c2[0][0], a0, b0); fma2(c2[0][1], a0, b1);
            fma2(c2[1][0], a1, b0); fma2(c2[1][1], a1, b1);
            fma2(c2[2][0], a2, b0); fma2(c2[2][1], a2, b1);
            fma2(c2[3][0], a3, b0); fma2(c2[3][1], a3, b1);
        }
    }
#pragma unroll
    for (int i = 0; i < 4; i++) {
        int m = ty * 4 + i;
#pragma unroll
        for (int p = 0; p < 2; p++) {
            float2 v = u2f(c2[i][p]);
            int col = n0 + tx * 4 + p * 2;
            float x0 = v.x, x1 = v.y;
            if (d.bias) { x0 += d.bias[col];                  x1 += d.bias[col + 1]; }
            if (d.add)  { x0 += d.add[(size_t)m * Hd + col];  x1 += d.add[(size_t)m * Hd + col + 1]; }
            d.C[(size_t)m * Hd + col] = x0;
            d.C[(size_t)m * Hd + col + 1] = x1;
        }
    }
}

// ---------------- fused softmax for both streams ----------------
__global__ void softmax2_k(const float* __restrict__ pv, const float* __restrict__ pt,
                           float* __restrict__ av, float* __restrict__ at) {
    __shared__ float buf[TVv];
    __shared__ float red[256];
    const int bb = blockIdx.x, tid = threadIdx.x;
    const float* part; float* out; int T, R, b;
    if (bb < Bsz) { part = pv; out = av; T = TVv; R = Bsz*TVv; b = bb; }
    else          { part = pt; out = at; T = TTt; R = Bsz*TTt; b = bb - Bsz; }
    for (int t = tid; t < T; t += 256) {
        float s = 0.f;
#pragma unroll
        for (int n = 0; n < NS; n++) s += part[(size_t)n * R + b * T + t];
        buf[t] = s;
    }
    __syncthreads();
    float m = -1e30f;
    for (int t = tid; t < T; t += 256) m = fmaxf(m, buf[t]);
    red[tid] = m; __syncthreads();
    for (int o = 128; o > 0; o >>= 1) { if (tid < o) red[tid] = fmaxf(red[tid], red[tid + o]); __syncthreads(); }
    m = red[0]; __syncthreads();
    float s = 0.f;
    for (int t = tid; t < T; t += 256) { float e = expf(buf[t] - m); buf[t] = e; s += e; }
    red[tid] = s; __syncthreads();
    for (int o = 128; o > 0; o >>= 1) { if (tid < o) red[tid] += red[tid + o]; __syncthreads(); }
    float inv = 1.f / red[0];
    for (int t = tid; t < T; t += 256) out[b * T + t] = buf[t] * inv;
}

// ---------------- fused weighted sums (reads bf16) ----------------
// One block per (stream,batch): 128 threads x 4 consecutive cols = 512 cols.
__global__ void wsum2_k(const __nv_bfloat16* __restrict__ Fb, const __nv_bfloat16* __restrict__ Tb,
                        const float* __restrict__ av, const float* __restrict__ at,
                        float* __restrict__ hv, float* __restrict__ ht) {
    __shared__ float as_[TVv];
    const int bb = blockIdx.x, tid = threadIdx.x;
    const __nv_bfloat16* X; const float* a; float* o; int T;
    if (bb < Bsz) { X = Fb + (size_t)bb * TVv * Hd; a = av + bb * TVv; o = hv + bb * Hd; T = TVv; }
    else { int b = bb - Bsz; X = Tb + (size_t)b * TTt * Hd; a = at + b * TTt; o = ht + b * Hd; T = TTt; }
    for (int t = tid; t < T; t += 128) as_[t] = a[t];
    __syncthreads();
    const int j0 = tid * 4;
    float a0 = 0.f, a1 = 0.f, a2 = 0.f, a3 = 0.f;
#pragma unroll 8
    for (int t = 0; t < T; t++) {
        float w = as_[t];
        ull v = *(const ull*)(X + (size_t)t * Hd + j0);
        __nv_bfloat162 lo = ((const __nv_bfloat162*)&v)[0];
        __nv_bfloat162 hi = ((const __nv_bfloat162*)&v)[1];
        float2 fl = __bfloat1622float2(lo);
        float2 fh = __bfloat1622float2(hi);
        a0 = fmaf(w, fl.x, a0); a1 = fmaf(w, fl.y, a1);
        a2 = fmaf(w, fh.x, a2); a3 = fmaf(w, fh.y, a3);
    }
    o[j0] = a0; o[j0 + 1] = a1; o[j0 + 2] = a2; o[j0 + 3] = a3;
}

// ---------------- gating logits ----------------
__global__ void logits_k(const float* __restrict__ mv1, const float* __restrict__ mt1,
                         const float* __restrict__ wb, float* __restrict__ lg) {
    __shared__ float red[128];
    const int r = blockIdx.x, tid = threadIdx.x;
    const float* row = (r < Bsz) ? (mv1 + (size_t)r * Hd) : (mt1 + (size_t)(r - Bsz) * Hd);
    float s = 0.f;
    for (int k = tid; k < Hd; k += 128) s += tanhf(row[k]) * wb[k];
    red[tid] = s; __syncthreads();
    for (int o = 64; o > 0; o >>= 1) { if (tid < o) red[tid] += red[tid + o]; __syncthreads(); }
    if (tid == 0) lg[r] = red[0];
}

__global__ void beta_k(const float* __restrict__ lg, float* __restrict__ beta) {
    __shared__ float red[128];
    __shared__ float ev[128];
    const int tid = threadIdx.x;
    float l = lg[tid];
    red[tid] = l; __syncthreads();
    for (int o = 64; o > 0; o >>= 1) { if (tid < o) red[tid] = fmaxf(red[tid], red[tid + o]); __syncthreads(); }
    float m = red[0]; __syncthreads();
    float e = expf(l - m);
    ev[tid] = e; red[tid] = e; __syncthreads();
    for (int o = 64; o > 0; o >>= 1) { if (tid < o) red[tid] += red[tid + o]; __syncthreads(); }
    if (tid == 0) { beta[0] = ev[0] / red[0]; beta[1] = ev[1] / red[0]; }
}

__global__ void final_k(const float* __restrict__ hWhh, const float* __restrict__ hv2,
                        const float* __restrict__ ht2, const float* __restrict__ bh,
                        const float* __restrict__ beta, float* __restrict__ out) {
    const int idx = blockIdx.x * blockDim.x + threadIdx.x;
    out[idx] = tanhf(hWhh[idx] + beta[0] * hv2[idx] + beta[1] * ht2[idx] + bh[idx & (Hd - 1)]);
}

// ---------------- host launcher ----------------
extern "C" void kernel_launch(void* const* d_in, const int* in_sizes, int n_in,
                              void* d_out, int out_size) {
    const float* h   = (const float*)d_in[0];
    const float* F   = (const float*)d_in[1];
    const float* Tx  = (const float*)d_in[2];
    const float* Wav = (const float*)d_in[3];
    const float* Wat = (const float*)d_in[4];
    const float* Uav = (const float*)d_in[5];
    const float* Uat = (const float*)d_in[6];
    const float* Vav = (const float*)d_in[7];
    const float* Vat = (const float*)d_in[8];
    const float* bav = (const float*)d_in[9];
    const float* bat = (const float*)d_in[10];
    const float* Whh = (const float*)d_in[11];
    const float* bh  = (const float*)d_in[12];
    const float* Wve = (const float*)d_in[13];
    const float* bve = (const float*)d_in[14];
    const float* Wqe = (const float*)d_in[15];
    const float* bqe = (const float*)d_in[16];
    const float* Wb  = (const float*)d_in[17];
    const float* Vbv = (const float*)d_in[18];
    const float* Vbt = (const float*)d_in[19];
    const float* bbv = (const float*)d_in[20];
    const float* bbt = (const float*)d_in[21];
    const float* wb  = (const float*)d_in[22];
    float* out = (float*)d_out;

    __nv_bfloat16 *Fb, *Tb, *WavT, *WatT;
    float *Uhv, *Uht, *Wbs, *hWhh, *pv, *pt, *av, *at,
          *hv, *ht, *hv2, *ht2, *mv1, *mt1, *lg, *beta;
    cudaGetSymbolAddress((void**)&Fb,   g_Fb);
    cudaGetSymbolAddress((void**)&Tb,   g_Tb);
    cudaGetSymbolAddress((void**)&WavT, g_WavT);
    cudaGetSymbolAddress((void**)&WatT, g_WatT);
    cudaGetSymbolAddress((void**)&Uhv,  g_Uhv);
    cudaGetSymbolAddress((void**)&Uht,  g_Uht);
    cudaGetSymbolAddress((void**)&Wbs,  g_Wbs);
    cudaGetSymbolAddress((void**)&hWhh, g_hWhh);
    cudaGetSymbolAddress((void**)&pv,   g_part_v);
    cudaGetSymbolAddress((void**)&pt,   g_part_t);
    cudaGetSymbolAddress((void**)&av,   g_av);
    cudaGetSymbolAddress((void**)&at,   g_at);
    cudaGetSymbolAddress((void**)&hv,   g_hv);
    cudaGetSymbolAddress((void**)&ht,   g_ht);
    cudaGetSymbolAddress((void**)&hv2,  g_hv2);
    cudaGetSymbolAddress((void**)&ht2,  g_ht2);
    cudaGetSymbolAddress((void**)&mv1,  g_mv1);
    cudaGetSymbolAddress((void**)&mt1,  g_mt1);
    cudaGetSymbolAddress((void**)&lg,   g_logits);
    cudaGetSymbolAddress((void**)&beta, g_beta);

    // bf16 conversions (weights transposed during conversion)
    cvt_bf16_k<<<(Bsz*TVv*Hd)/2048, 256>>>(F,  Fb);
    cvt_bf16_k<<<(Bsz*TTt*Hd)/2048, 256>>>(Tx, Tb);
    cvt_wt_k<<<dim3(16,16), dim3(32,8)>>>(Wav, WavT);
    cvt_wt_k<<<dim3(16,16), dim3(32,8)>>>(Wat, WatT);

    // Conditioning GEMMs: h @ {Uav, Uat, Wb, Whh} in one launch
    GDesc4 p1;
    p1.g[0] = { h, Uav, Uhv,  nullptr, nullptr, 0 };
    p1.g[1] = { h, Uat, Uht,  nullptr, nullptr, 0 };
    p1.g[2] = { h, Wb,  Wbs,  nullptr, nullptr, 0 };
    p1.g[3] = { h, Whh, hWhh, nullptr, nullptr, 0 };
    sgemm4<<<dim3(8, 4), 256>>>(p1);

    // Tensor-core fused score GEMMs (B = W^T, k-contiguous)
    score_mma<<<dim3(4, (Bsz*TVv)/128), 256>>>(Fb, WavT, Uhv, bav, Vav, pv, TVv, Bsz*TVv);
    score_mma<<<dim3(4, (Bsz*TTt)/128), 256>>>(Tb, WatT, Uht, bat, Vat, pt, TTt, Bsz*TTt);

    // Softmax + weighted sums, both streams fused per launch
    softmax2_k<<<2*Bsz, 256>>>(pv, pt, av, at);
    wsum2_k<<<2*Bsz, 128>>>(Fb, Tb, av, at, hv, ht);

    // Encoders + gate pre-activations in one launch (trans handles the .T)
    GDesc4 p2;
    p2.g[0] = { hv, Wve, hv2, bve, nullptr, 1 };
    p2.g[1] = { ht, Wqe, ht2, bqe, nullptr, 1 };
    p2.g[2] = { hv, Vbv, mv1, bbv, Wbs,     0 };
    p2.g[3] = { ht, Vbt, mt1, bbt, Wbs,     0 };
    sgemm4<<<dim3(8, 4), 256>>>(p2);

    // Gate + output
    logits_k<<<2*Bsz, 128>>>(mv1, mt1, wb, lg);
    beta_k<<<1, 128>>>(lg, beta);
    final_k<<<Bsz, Hd>>>(hWhh, hv2, ht2, bh, beta, out);
}

// round 11
// speedup vs baseline: 10.3644x; 1.1521x over previous
#include <cuda_runtime.h>
#include <cuda_bf16.h>
#include <cstdint>
#include <cstddef>

#define Bsz 64
#define Hd  512
#define TVv 512
#define TTt 64
#define NS  8          // partial slices for score reduction (4 n-CTAs x 2 n-warps)

typedef unsigned long long ull;

// ---------------- device scratch (no runtime allocation allowed) ----------------
__device__ __nv_bfloat16 g_Fb  [Bsz*TVv*Hd];   // bf16 copy of hidden_frames
__device__ __nv_bfloat16 g_Tb  [Bsz*TTt*Hd];   // bf16 copy of hidden_text
__device__ __nv_bfloat16 g_WavT[Hd*Hd];        // bf16 transposed Wav  [n][k]
__device__ __nv_bfloat16 g_WatT[Hd*Hd];        // bf16 transposed Wat  [n][k]

__device__ float g_Uhv [Bsz*Hd];
__device__ float g_Uht [Bsz*Hd];
__device__ float g_Wbs [Bsz*Hd];
__device__ float g_hWhh[Bsz*Hd];
__device__ float g_part_v[NS*Bsz*TVv];
__device__ float g_part_t[NS*Bsz*TTt];
__device__ float g_hv [Bsz*Hd];
__device__ float g_ht [Bsz*Hd];
__device__ float g_hv2[Bsz*Hd];
__device__ float g_ht2[Bsz*Hd];
__device__ float g_mv1[Bsz*Hd];
__device__ float g_mt1[Bsz*Hd];
__device__ float g_logits[2*Bsz];

// ---------------- small helpers ----------------
__device__ __forceinline__ uint32_t pack_bf16(float lo, float hi) {
    uint32_t r;
    asm("cvt.rn.bf16x2.f32 %0, %1, %2;" : "=r"(r) : "f"(hi), "f"(lo));
    return r;
}
__device__ __forceinline__ uint32_t s2u(const void* p) {
    return (uint32_t)__cvta_generic_to_shared(p);
}
__device__ __forceinline__ void cp16(uint32_t dst, const void* src) {
    asm volatile("cp.async.cg.shared.global [%0], [%1], 16;" :: "r"(dst), "l"(src));
}
__device__ __forceinline__ float tanh_fast(float x) {
    float y; asm("tanh.approx.f32 %0, %1;" : "=f"(y) : "f"(x)); return y;
}
__device__ __forceinline__ ull dup2(float x) {
    ull r; unsigned u = __float_as_uint(x);
    asm("mov.b64 %0, {%1, %1};" : "=l"(r) : "r"(u));
    return r;
}
__device__ __forceinline__ void fma2(ull &d, ull a, ull b) {
    asm("fma.rn.f32x2 %0, %1, %2, %3;" : "=l"(d) : "l"(a), "l"(b), "l"(d));
}
__device__ __forceinline__ float2 u2f(ull v) {
    float2 f;
    f.x = __uint_as_float((unsigned)(v & 0xffffffffu));
    f.y = __uint_as_float((unsigned)(v >> 32));
    return f;
}
__device__ __forceinline__ void mma_bf16(float* c, const uint32_t* a, uint32_t b0, uint32_t b1) {
    asm volatile(
        "mma.sync.aligned.m16n8k16.row.col.f32.bf16.bf16.f32 "
        "{%0,%1,%2,%3}, {%4,%5,%6,%7}, {%8,%9}, {%0,%1,%2,%3};"
        : "+f"(c[0]), "+f"(c[1]), "+f"(c[2]), "+f"(c[3])
        : "r"(a[0]), "r"(a[1]), "r"(a[2]), "r"(a[3]), "r"(b0), "r"(b1));
}

// ---------------- fp32 -> bf16 conversion (8 elems / thread) ----------------
__global__ void cvt_bf16_k(const float* __restrict__ src, __nv_bfloat16* __restrict__ dst) {
    size_t i = ((size_t)blockIdx.x * 256 + threadIdx.x) * 8;
    float4 v0 = *(const float4*)(src + i);
    float4 v1 = *(const float4*)(src + i + 4);
    uint4 o;
    o.x = pack_bf16(v0.x, v0.y); o.y = pack_bf16(v0.z, v0.w);
    o.z = pack_bf16(v1.x, v1.y); o.w = pack_bf16(v1.z, v1.w);
    *(uint4*)(dst + i) = o;
}

// ---------------- fp32 W[k][n] -> bf16 W^T[n][k] ----------------
__global__ void cvt_wt_k(const float* __restrict__ in, __nv_bfloat16* __restrict__ out) {
    __shared__ float tile[32][33];
    int x  = blockIdx.x * 32 + threadIdx.x;
    int y0 = blockIdx.y * 32;
#pragma unroll
    for (int i = threadIdx.y; i < 32; i += 8)
        tile[i][threadIdx.x] = in[(size_t)(y0 + i) * Hd + x];
    __syncthreads();
    int k   = y0 + threadIdx.x;
    int nb0 = blockIdx.x * 32;
#pragma unroll
    for (int i = threadIdx.y; i < 32; i += 8)
        out[(size_t)(nb0 + i) * Hd + k] = __float2bfloat16(tile[threadIdx.x][i]);
}

// ---------------- bf16 tensor-core score kernel ----------------
// partial[slice*R + row] = sum_{j in 64-col slice} V[j]*tanh((A@W)[row,j] + Uh[b,j] + sbias[j])
#define ASTR 40

__device__ __forceinline__ void score_issue(const __nv_bfloat16* Ag, const __nv_bfloat16* WT,
                                            int n0, int c, __nv_bfloat16* as, __nv_bfloat16* bs, int tid)
{
#pragma unroll
    for (int i = 0; i < 2; i++) {           // A: 128 rows x 32 bf16
        int e = tid + i * 256;
        int r = e >> 2, seg = e & 3;
        cp16(s2u(as + r * ASTR + seg * 8), Ag + (size_t)r * Hd + c * 32 + seg * 8);
    }
#pragma unroll
    for (int i = 0; i < 2; i++) {           // B: 128 n-rows x 32 k bf16
        int e = tid + i * 256;
        int r = e >> 2, seg = e & 3;
        cp16(s2u(bs + r * ASTR + seg * 8), WT + (size_t)(n0 + r) * Hd + c * 32 + seg * 8);
    }
    asm volatile("cp.async.commit_group;" ::: "memory");
}

__global__ void __launch_bounds__(256, 2)
score_mma(const __nv_bfloat16* __restrict__ A, const __nv_bfloat16* __restrict__ WT,
          const float* __restrict__ Uh, const float* __restrict__ sbias,
          const float* __restrict__ V, float* __restrict__ partial, int T, int R)
{
    __shared__ __align__(16) __nv_bfloat16 As[2][128 * ASTR];
    __shared__ __align__(16) __nv_bfloat16 Bs[2][128 * ASTR];

    const int tid  = threadIdx.x;
    const int lane = tid & 31, wid = tid >> 5;
    const int wm = wid & 3, wn = wid >> 2;
    const int gid = lane >> 2, tig = lane & 3;
    const int n0 = blockIdx.x * 128;
    const int m0 = blockIdx.y * 128;
    const __nv_bfloat16* Ag = A + (size_t)m0 * Hd;

    float acc[2][8][4];
#pragma unroll
    for (int a = 0; a < 2; a++)
#pragma unroll
        for (int b = 0; b < 8; b++)
#pragma unroll
            for (int c = 0; c < 4; c++) acc[a][b][c] = 0.f;

    score_issue(Ag, WT, n0, 0, As[0], Bs[0], tid);

#pragma unroll 1
    for (int c = 0; c < 16; c++) {
        if (c + 1 < 16) {
            score_issue(Ag, WT, n0, c + 1, As[(c + 1) & 1], Bs[(c + 1) & 1], tid);
            asm volatile("cp.async.wait_group 1;" ::: "memory");
        } else {
            asm volatile("cp.async.wait_group 0;" ::: "memory");
        }
        __syncthreads();
        const __nv_bfloat16* as = As[c & 1];
        const __nv_bfloat16* bs = Bs[c & 1];
#pragma unroll
        for (int kf = 0; kf < 2; kf++) {
            const int c0 = kf * 16 + tig * 2;
            uint32_t af[2][4];
#pragma unroll
            for (int mf = 0; mf < 2; mf++) {
                int r = wm * 32 + mf * 16 + gid;
                af[mf][0] = *(const uint32_t*)(as + r * ASTR + c0);
                af[mf][1] = *(const uint32_t*)(as + (r + 8) * ASTR + c0);
                af[mf][2] = *(const uint32_t*)(as + r * ASTR + c0 + 8);
                af[mf][3] = *(const uint32_t*)(as + (r + 8) * ASTR + c0 + 8);
            }
#pragma unroll
            for (int nf = 0; nf < 8; nf++) {
                int n = wn * 64 + nf * 8 + gid;
                uint32_t b0 = *(const uint32_t*)(bs + n * ASTR + c0);
                uint32_t b1 = *(const uint32_t*)(bs + n * ASTR + c0 + 8);
                mma_bf16(acc[0][nf], af[0], b0, b1);
                mma_bf16(acc[1][nf], af[1], b0, b1);
            }
        }
        __syncthreads();
    }

    const int base_m = m0 + wm * 32;
    float s[2][2];
#pragma unroll
    for (int mf = 0; mf < 2; mf++) {
#pragma unroll
        for (int h = 0; h < 2; h++) {
            int row = base_m + mf * 16 + h * 8 + gid;
            int b = row / T;
            const float* UhR = Uh + (size_t)b * Hd;
            float ss = 0.f;
#pragma unroll
            for (int nf = 0; nf < 8; nf++) {
#pragma unroll
                for (int e = 0; e < 2; e++) {
                    int col = n0 + wn * 64 + nf * 8 + tig * 2 + e;
                    float x = acc[mf][nf][h * 2 + e] + UhR[col] + sbias[col];
                    ss += V[col] * tanh_fast(x);
                }
            }
            s[mf][h] = ss;
        }
    }
#pragma unroll
    for (int mf = 0; mf < 2; mf++)
#pragma unroll
        for (int h = 0; h < 2; h++) {
            s[mf][h] += __shfl_xor_sync(0xffffffffu, s[mf][h], 1);
            s[mf][h] += __shfl_xor_sync(0xffffffffu, s[mf][h], 2);
        }
    if (tig == 0) {
        const int slice = blockIdx.x * 2 + wn;
#pragma unroll
        for (int mf = 0; mf < 2; mf++)
#pragma unroll
            for (int h = 0; h < 2; h++)
                partial[(size_t)slice * R + base_m + mf * 16 + h * 8 + gid] = s[mf][h];
    }
}

// ---------------- fused skinny GEMMs: 4 gemms per launch ----------------
struct GDesc { const float* A; const float* W; float* C; const float* bias; const float* add; int trans; };
struct GDesc4 { GDesc g[4]; };

__global__ void __launch_bounds__(256, 4)
sgemm4(GDesc4 ds) {
    const GDesc d = ds.g[blockIdx.y];
    const int n0 = blockIdx.x * 64;
    __shared__ float Asm[32][68];  // [k][m]
    __shared__ float Bsm[32][68];  // [k][n]
    const int tid = threadIdx.x;
    const int tx = tid & 15, ty = tid >> 4;

    ull c2[4][2];
#pragma unroll
    for (int i = 0; i < 4; i++) { c2[i][0] = 0ull; c2[i][1] = 0ull; }

    for (int kt = 0; kt < Hd; kt += 32) {
        __syncthreads();
#pragma unroll
        for (int i = 0; i < 2; i++) {
            int f = tid + i * 256;
            int m = f >> 3, ko = (f & 7) * 4;
            float4 v = *(const float4*)(d.A + (size_t)m * Hd + kt + ko);
            Asm[ko][m] = v.x; Asm[ko + 1][m] = v.y; Asm[ko + 2][m] = v.z; Asm[ko + 3][m] = v.w;
        }
        if (!d.trans) {
#pragma unroll
            for (int i = 0; i < 2; i++) {
                int f = tid + i * 256;
                int k = f >> 4, nn = (f & 15) * 4;
                float4 v = *(const float4*)(d.W + (size_t)(kt + k) * Hd + n0 + nn);
                *(float4*)&Bsm[k][nn] = v;
            }
        } else {
#pragma unroll
            for (int i = 0; i < 2; i++) {
                int f = tid + i * 256;
                int nn = f >> 3, ko = (f & 7) * 4;
                float4 v = *(const float4*)(d.W + (size_t)(n0 + nn) * Hd + kt + ko);
                Bsm[ko][nn] = v.x; Bsm[ko + 1][nn] = v.y; Bsm[ko + 2][nn] = v.z; Bsm[ko + 3][nn] = v.w;
            }
        }
        __syncthreads();
#pragma unroll
        for (int k = 0; k < 32; k++) {
            float4 a = *(const float4*)&Asm[k][ty * 4];
            const ull* bp = (const ull*)&Bsm[k][tx * 4];
            ull b0 = bp[0], b1 = bp[1];
            ull a0 = dup2(a.x), a1 = dup2(a.y), a2 = dup2(a.z), a3 = dup2(a.w);
            fma2(c2[0][0], a0, b0); fma2(c2[0][1], a0, b1);
            fma2(c2[1][0], a1, b0); fma2(c2[1][1], a1, b1);
            fma2(c2[2][0], a2, b0); fma2(c2[2][1], a2, b1);
            fma2(c2[3][0], a3, b0); fma2(c2[3][1], a3, b1);
        }
    }
#pragma unroll
    for (int i = 0; i < 4; i++) {
        int m = ty * 4 + i;
#pragma unroll
        for (int p = 0; p < 2; p++) {
            float2 v = u2f(c2[i][p]);
            int col = n0 + tx * 4 + p * 2;
            float x0 = v.x, x1 = v.y;
            if (d.bias) { x0 += d.bias[col];                  x1 += d.bias[col + 1]; }
            if (d.add)  { x0 += d.add[(size_t)m * Hd + col];  x1 += d.add[(size_t)m * Hd + col + 1]; }
            d.C[(size_t)m * Hd + col] = x0;
            d.C[(size_t)m * Hd + col + 1] = x1;
        }
    }
}

// ---------------- fused softmax + weighted sum (per stream/batch block) ----------------
// Block bb<64: frames batch bb; bb>=64: text batch bb-64. Softmax weights kept in smem,
// normalization folded into the final scale. Output hv/ht[b, :512], 256 thr x 2 cols.
__global__ void __launch_bounds__(256)
softmax_wsum_k(const float* __restrict__ pv, const float* __restrict__ pt,
               const __nv_bfloat16* __restrict__ Fb, const __nv_bfloat16* __restrict__ Tb,
               float* __restrict__ hv, float* __restrict__ ht)
{
    __shared__ float buf[TVv];
    __shared__ float red[256];
    const int bb = blockIdx.x, tid = threadIdx.x;
    const float* part; const __nv_bfloat16* X; float* o; int T, R, b;
    if (bb < Bsz) { b = bb;       part = pv; X = Fb + (size_t)b * TVv * Hd; o = hv + b * Hd; T = TVv; R = Bsz*TVv; }
    else          { b = bb - Bsz; part = pt; X = Tb + (size_t)b * TTt * Hd; o = ht + b * Hd; T = TTt; R = Bsz*TTt; }

    for (int t = tid; t < T; t += 256) {
        float s = 0.f;
#pragma unroll
        for (int n = 0; n < NS; n++) s += part[(size_t)n * R + b * T + t];
        buf[t] = s;
    }
    __syncthreads();
    float m = -1e30f;
    for (int t = tid; t < T; t += 256) m = fmaxf(m, buf[t]);
    red[tid] = m; __syncthreads();
    for (int o2 = 128; o2 > 0; o2 >>= 1) { if (tid < o2) red[tid] = fmaxf(red[tid], red[tid + o2]); __syncthreads(); }
    m = red[0]; __syncthreads();
    float s = 0.f;
    for (int t = tid; t < T; t += 256) { float e = expf(buf[t] - m); buf[t] = e; s += e; }
    red[tid] = s; __syncthreads();
    for (int o2 = 128; o2 > 0; o2 >>= 1) { if (tid < o2) red[tid] += red[tid + o2]; __syncthreads(); }
    const float inv = 1.f / red[0];
    __syncthreads();

    // weighted sum with unnormalized weights, scale at the end
    const int j0 = tid * 2;
    float a0 = 0.f, a1 = 0.f;
#pragma unroll 8
    for (int t = 0; t < T; t++) {
        float w = buf[t];
        __nv_bfloat162 v = *(const __nv_bfloat162*)(X + (size_t)t * Hd + j0);
        float2 f = __bfloat1622float2(v);
        a0 = fmaf(w, f.x, a0);
        a1 = fmaf(w, f.y, a1);
    }
    o[j0]     = a0 * inv;
    o[j0 + 1] = a1 * inv;
}

// ---------------- gating logits ----------------
__global__ void logits_k(const float* __restrict__ mv1, const float* __restrict__ mt1,
                         const float* __restrict__ wb, float* __restrict__ lg) {
    __shared__ float red[128];
    const int r = blockIdx.x, tid = threadIdx.x;
    const float* row = (r < Bsz) ? (mv1 + (size_t)r * Hd) : (mt1 + (size_t)(r - Bsz) * Hd);
    float s = 0.f;
    for (int k = tid; k < Hd; k += 128) s += tanhf(row[k]) * wb[k];
    red[tid] = s; __syncthreads();
    for (int o = 64; o > 0; o >>= 1) { if (tid < o) red[tid] += red[tid + o]; __syncthreads(); }
    if (tid == 0) lg[r] = red[0];
}

// ---------------- final output with inline beta (softmax over 128 logits) ----------------
__global__ void __launch_bounds__(256)
final2_k(const float* __restrict__ hWhh, const float* __restrict__ hv2,
         const float* __restrict__ ht2, const float* __restrict__ bh,
         const float* __restrict__ lg, float* __restrict__ out)
{
    __shared__ float red[128];
    __shared__ float ev01[2];
    const int tid = threadIdx.x;
    if (tid < 128) red[tid] = lg[tid];
    __syncthreads();
    // max over 128
    if (tid < 64) red[tid] = fmaxf(red[tid], red[tid + 64]);
    __syncthreads();
    if (tid < 32) red[tid] = fmaxf(red[tid], red[tid + 32]);
    __syncthreads();
    if (tid < 16) red[tid] = fmaxf(red[tid], red[tid + 16]);
    __syncthreads();
    if (tid < 8) red[tid] = fmaxf(red[tid], red[tid + 8]);
    __syncthreads();
    if (tid < 4) red[tid] = fmaxf(red[tid], red[tid + 4]);
    __syncthreads();
    if (tid < 2) red[tid] = fmaxf(red[tid], red[tid + 2]);
    __syncthreads();
    float m = fmaxf(red[0], red[1]);
    __syncthreads();
    float e = (tid < 128) ? expf(lg[tid] - m) : 0.f;
    if (tid < 2) ev01[tid] = e;
    if (tid < 128) red[tid] = e;
    __syncthreads();
    for (int o = 64; o > 0; o >>= 1) { if (tid < o) red[tid] += red[tid + o]; __syncthreads(); }
    const float inv = 1.f / red[0];
    const float b0 = ev01[0] * inv, b1 = ev01[1] * inv;

    const int idx = blockIdx.x * 256 + tid;
    out[idx] = tanhf(hWhh[idx] + b0 * hv2[idx] + b1 * ht2[idx] + bh[idx & (Hd - 1)]);
}

// ---------------- host launcher (multi-stream fork-join graph) ----------------
extern "C" void kernel_launch(void* const* d_in, const int* in_sizes, int n_in,
                              void* d_out, int out_size) {
    const float* h   = (const float*)d_in[0];
    const float* F   = (const float*)d_in[1];
    const float* Tx  = (const float*)d_in[2];
    const float* Wav = (const float*)d_in[3];
    const float* Wat = (const float*)d_in[4];
    const float* Uav = (const float*)d_in[5];
    const float* Uat = (const float*)d_in[6];
    const float* Vav = (const float*)d_in[7];
    const float* Vat = (const float*)d_in[8];
    const float* bav = (const float*)d_in[9];
    const float* bat = (const float*)d_in[10];
    const float* Whh = (const float*)d_in[11];
    const float* bh  = (const float*)d_in[12];
    const float* Wve = (const float*)d_in[13];
    const float* bve = (const float*)d_in[14];
    const float* Wqe = (const float*)d_in[15];
    const float* bqe = (const float*)d_in[16];
    const float* Wb  = (const float*)d_in[17];
    const float* Vbv = (const float*)d_in[18];
    const float* Vbt = (const float*)d_in[19];
    const float* bbv = (const float*)d_in[20];
    const float* bbt = (const float*)d_in[21];
    const float* wb  = (const float*)d_in[22];
    float* out = (float*)d_out;

    __nv_bfloat16 *Fb, *Tb, *WavT, *WatT;
    float *Uhv, *Uht, *Wbs, *hWhh, *pv, *pt, *hv, *ht, *hv2, *ht2, *mv1, *mt1, *lg;
    cudaGetSymbolAddress((void**)&Fb,   g_Fb);
    cudaGetSymbolAddress((void**)&Tb,   g_Tb);
    cudaGetSymbolAddress((void**)&WavT, g_WavT);
    cudaGetSymbolAddress((void**)&WatT, g_WatT);
    cudaGetSymbolAddress((void**)&Uhv,  g_Uhv);
    cudaGetSymbolAddress((void**)&Uht,  g_Uht);
    cudaGetSymbolAddress((void**)&Wbs,  g_Wbs);
    cudaGetSymbolAddress((void**)&hWhh, g_hWhh);
    cudaGetSymbolAddress((void**)&pv,   g_part_v);
    cudaGetSymbolAddress((void**)&pt,   g_part_t);
    cudaGetSymbolAddress((void**)&hv,   g_hv);
    cudaGetSymbolAddress((void**)&ht,   g_ht);
    cudaGetSymbolAddress((void**)&hv2,  g_hv2);
    cudaGetSymbolAddress((void**)&ht2,  g_ht2);
    cudaGetSymbolAddress((void**)&mv1,  g_mv1);
    cudaGetSymbolAddress((void**)&mt1,  g_mt1);
    cudaGetSymbolAddress((void**)&lg,   g_logits);

    // Streams/events created once, on the first (non-captured correctness) call.
    // Work issued per call is identical and deterministic; under graph capture the
    // event record/wait pairs become graph edges (standard fork-join pattern).
    static cudaStream_t s1 = nullptr, s2 = nullptr;
    static cudaEvent_t e0 = nullptr, e1 = nullptr, e2 = nullptr, ep1 = nullptr;
    if (!s1) {
        cudaStreamCreateWithFlags(&s1, cudaStreamNonBlocking);
        cudaStreamCreateWithFlags(&s2, cudaStreamNonBlocking);
        cudaEventCreateWithFlags(&e0,  cudaEventDisableTiming);
        cudaEventCreateWithFlags(&e1,  cudaEventDisableTiming);
        cudaEventCreateWithFlags(&e2,  cudaEventDisableTiming);
        cudaEventCreateWithFlags(&ep1, cudaEventDisableTiming);
    }

    // Fork
    cudaEventRecord(e0, 0);
    cudaStreamWaitEvent(s1, e0, 0);
    cudaStreamWaitEvent(s2, e0, 0);

    // --- branch s1: conditioning GEMMs + Wav transpose (feeds score_v) ---
    GDesc4 p1;
    p1.g[0] = { h, Uav, Uhv,  nullptr, nullptr, 0 };
    p1.g[1] = { h, Uat, Uht,  nullptr, nullptr, 0 };
    p1.g[2] = { h, Wb,  Wbs,  nullptr, nullptr, 0 };
    p1.g[3] = { h, Whh, hWhh, nullptr, nullptr, 0 };
    sgemm4<<<dim3(8, 4), 256, 0, s1>>>(p1);
    cudaEventRecord(ep1, s1);                       // Uht ready (for text branch)
    cvt_wt_k<<<dim3(16,16), dim3(32,8), 0, s1>>>(Wav, WavT);
    cudaEventRecord(e1, s1);                        // Uhv + WavT ready

    // --- branch s2: entire text stream ---
    cvt_bf16_k<<<(Bsz*TTt*Hd)/2048, 256, 0, s2>>>(Tx, Tb);
    cvt_wt_k<<<dim3(16,16), dim3(32,8), 0, s2>>>(Wat, WatT);
    cudaStreamWaitEvent(s2, ep1, 0);                // needs Uht
    score_mma<<<dim3(4, (Bsz*TTt)/128), 256, 0, s2>>>(Tb, WatT, Uht, bat, Vat, pt, TTt, Bsz*TTt);
    cudaEventRecord(e2, s2);                        // pt + Tb ready

    // --- main stream: frames stream (critical path) ---
    cvt_bf16_k<<<(Bsz*TVv*Hd)/2048, 256>>>(F, Fb);
    cudaStreamWaitEvent(0, e1, 0);
    score_mma<<<dim3(4, (Bsz*TVv)/128), 256>>>(Fb, WavT, Uhv, bav, Vav, pv, TVv, Bsz*TVv);

    // Join text branch, then fused softmax+wsum for both streams
    cudaStreamWaitEvent(0, e2, 0);
    softmax_wsum_k<<<2*Bsz, 256>>>(pv, pt, Fb, Tb, hv, ht);

    // Encoders + gate pre-activations (needs hv/ht and Wbs; Wbs ordered via e1)
    GDesc4 p2;
    p2.g[0] = { hv, Wve, hv2, bve, nullptr, 1 };
    p2.g[1] = { ht, Wqe, ht2, bqe, nullptr, 1 };
    p2.g[2] = { hv, Vbv, mv1, bbv, Wbs,     0 };
    p2.g[3] = { ht, Vbt, mt1, bbt, Wbs,     0 };
    sgemm4<<<dim3(8, 4), 256>>>(p2);

    // Gate + output (beta folded into final2_k)
    logits_k<<<2*Bsz, 128>>>(mv1, mt1, wb, lg);
    final2_k<<<(Bsz*Hd)/256, 256>>>(hWhh, hv2, ht2, bh, lg, out);
}